// round 6
// baseline (speedup 1.0000x reference)
#include <cuda_runtime.h>
#include <cuda_fp16.h>
#include <cstdint>

// Problem constants
#define BB 16
#define TT 4096
#define DD 768
#define NBOX 1024
#define MAXB 128
#define DDETR 256
#define VIS_ELEMS (BB*MAXB*DD)
#define MASK_ELEMS (BB*MAXB)
#define NC 64

// ---------------- scratch (device globals) -----------------------------------
__device__ __align__(16) float g_partial[BB*NC*DD];
__device__ __align__(16) float g_x[BB*DD];
__device__ __align__(16) float g_h1t[BB*DD];
__device__ __align__(16) float g_h1d[BB*DD];
__device__ __align__(16) float g_xt[BB*DD];
__device__ __align__(16) float g_hb[BB*DD];          // folded bias for gemm_h
__device__ int g_pos[NBOX];

// fp16 hi/lo operand arrays (row-major, k contiguous)
__device__ __align__(16) __half g_w1h[768*256],  g_w1l[768*256];
__device__ __align__(16) __half g_w2h[768*768],  g_w2l[768*768];
__device__ __align__(16) __half g_wph[768*768],  g_wpl[768*768];   // pw[:,768:]
__device__ __align__(16) __half g_feath[1024*256], g_featl[1024*256];
__device__ __align__(16) __half g_fm1h[1024*768],  g_fm1l[1024*768];
__device__ __align__(16) __half g_fmh[1024*768],   g_fml[1024*768];

// ---------------- helpers -------------------------------------------------------
__device__ __forceinline__ uint32_t smem_u32(const void* p) {
    uint32_t r;
    asm("{ .reg .u64 t; cvta.to.shared.u64 t, %1; cvt.u32.u64 %0, t; }"
        : "=r"(r) : "l"(p));
    return r;
}
#define CP_ASYNC16(dst, src) \
    asm volatile("cp.async.cg.shared.global [%0], [%1], 16;" \
                 :: "r"(dst), "l"(src) : "memory")
#define CP_COMMIT() asm volatile("cp.async.commit_group;" ::: "memory")
#define CP_WAIT(n)  asm volatile("cp.async.wait_group %0;" :: "n"(n) : "memory")

#define LDSM_X4(r0, r1, r2, r3, addr) \
    asm volatile("ldmatrix.sync.aligned.m8n8.x4.shared.b16 {%0,%1,%2,%3}, [%4];" \
                 : "=r"(r0), "=r"(r1), "=r"(r2), "=r"(r3) : "r"(addr))

__device__ __forceinline__ void h2split(float v, __half2* oh, __half2* ol,
                                        float v1) {
    __half h0 = __float2half_rn(v),  h1 = __float2half_rn(v1);
    __half l0 = __float2half_rn(v - __half2float(h0));
    __half l1 = __float2half_rn(v1 - __half2float(h1));
    *oh = __halves2half2(h0, h1);
    *ol = __halves2half2(l0, l1);
}

// ---------------- zero vis_output ----------------------------------------------
__global__ void zero_vis_kernel(float4* __restrict__ out) {
    const int n4 = VIS_ELEMS / 4;
    for (int i = blockIdx.x * blockDim.x + threadIdx.x; i < n4;
         i += gridDim.x * blockDim.x)
        out[i] = make_float4(0.f, 0.f, 0.f, 0.f);
}

// ---------------- mean pass 1 ----------------------------------------------------
__global__ void mean_partial_kernel(const float* __restrict__ in) {
    int b = blockIdx.x >> 6;
    int c = blockIdx.x & 63;
    const float4* p = reinterpret_cast<const float4*>(
        in + ((size_t)b * TT + (size_t)c * 64) * DD) + threadIdx.x;
    float4 acc = make_float4(0.f, 0.f, 0.f, 0.f);
    #pragma unroll 8
    for (int r = 0; r < 64; r++) {
        float4 v = p[(size_t)r * (DD / 4)];
        acc.x += v.x; acc.y += v.y; acc.z += v.z; acc.w += v.w;
    }
    reinterpret_cast<float4*>(g_partial + ((size_t)b * NC + c) * DD)[threadIdx.x] = acc;
}

// ---------------- mean pass 2 ----------------------------------------------------
__global__ void mean_final_kernel() {
    int i = blockIdx.x * blockDim.x + threadIdx.x;
    int b  = i / (DD / 4);
    int c4 = i % (DD / 4);
    const float4* p = reinterpret_cast<const float4*>(g_partial)
                      + (size_t)b * NC * (DD / 4) + c4;
    float4 acc = make_float4(0.f, 0.f, 0.f, 0.f);
    #pragma unroll 8
    for (int c = 0; c < NC; c++) {
        float4 v = p[(size_t)c * (DD / 4)];
        acc.x += v.x; acc.y += v.y; acc.z += v.z; acc.w += v.w;
    }
    const float s = 1.0f / (float)TT;
    acc.x *= s; acc.y *= s; acc.z *= s; acc.w *= s;
    reinterpret_cast<float4*>(g_x)[(size_t)b * (DD / 4) + c4] = acc;
}

// ---------------- small MLP: smem-staged x, 4 cols/warp ---------------------------
__global__ __launch_bounds__(256) void mlp_kernel(int layer,
        const float* __restrict__ wt, const float* __restrict__ bt,
        const float* __restrict__ wd, const float* __restrict__ bd,
        float* __restrict__ retx_out) {
    __shared__ __align__(16) float xs[BB * DD];
    int branch = blockIdx.x / 24;
    const float* in   = (layer == 0) ? g_x : (branch ? g_h1d : g_h1t);
    const float* w    = branch ? wd : wt;
    const float* bias = branch ? bd : bt;
    float* out        = (layer == 0) ? (branch ? g_h1d : g_h1t)
                                     : (branch ? retx_out : g_xt);
    {
        const float4* s = reinterpret_cast<const float4*>(in);
        float4* d = reinterpret_cast<float4*>(xs);
        for (int i = threadIdx.x; i < BB * DD / 4; i += 256) d[i] = s[i];
    }
    __syncthreads();

    int warp = threadIdx.x >> 5, lane = threadIdx.x & 31;
    int j0 = (blockIdx.x % 24) * 32 + warp * 4;
    float acc[4][BB];
#pragma unroll
    for (int j = 0; j < 4; j++)
#pragma unroll
        for (int b = 0; b < BB; b++) acc[j][b] = 0.f;

    for (int it = 0; it < DD / 128; it++) {
        int k = it * 128 + lane * 4;
        float4 wv[4];
#pragma unroll
        for (int j = 0; j < 4; j++)
            wv[j] = *reinterpret_cast<const float4*>(&w[(size_t)(j0 + j) * DD + k]);
#pragma unroll
        for (int b = 0; b < BB; b++) {
            float4 xv = *reinterpret_cast<const float4*>(&xs[b * DD + k]);
#pragma unroll
            for (int j = 0; j < 4; j++) {
                acc[j][b] = fmaf(wv[j].x, xv.x, acc[j][b]);
                acc[j][b] = fmaf(wv[j].y, xv.y, acc[j][b]);
                acc[j][b] = fmaf(wv[j].z, xv.z, acc[j][b]);
                acc[j][b] = fmaf(wv[j].w, xv.w, acc[j][b]);
            }
        }
    }
#pragma unroll
    for (int j = 0; j < 4; j++)
#pragma unroll
        for (int b = 0; b < BB; b++)
#pragma unroll
            for (int off = 16; off > 0; off >>= 1)
                acc[j][b] += __shfl_xor_sync(0xFFFFFFFFu, acc[j][b], off);
    if (lane == 0) {
#pragma unroll
        for (int j = 0; j < 4; j++) {
            float bb = bias[j0 + j];
#pragma unroll
            for (int b = 0; b < BB; b++) {
                float v = acc[j][b] + bb;
                if (layer == 0) v = fmaxf(v, 0.f);
                out[b * DD + j0 + j] = v;
            }
        }
    }
}

// ---------------- hb = pb + xt @ pw[:, :768]^T -----------------------------------
__global__ __launch_bounds__(256) void hb_kernel(const float* __restrict__ pw,
                                                 const float* __restrict__ pb) {
    __shared__ __align__(16) float xs[BB * DD];
    {
        const float4* s = reinterpret_cast<const float4*>(g_xt);
        float4* d = reinterpret_cast<float4*>(xs);
        for (int i = threadIdx.x; i < BB * DD / 4; i += 256) d[i] = s[i];
    }
    __syncthreads();
    int warp = threadIdx.x >> 5, lane = threadIdx.x & 31;
    int j0 = blockIdx.x * 32 + warp * 4;
    float acc[4][BB];
#pragma unroll
    for (int j = 0; j < 4; j++)
#pragma unroll
        for (int b = 0; b < BB; b++) acc[j][b] = 0.f;
    for (int it = 0; it < DD / 128; it++) {
        int k = it * 128 + lane * 4;
        float4 wv[4];
#pragma unroll
        for (int j = 0; j < 4; j++)
            wv[j] = *reinterpret_cast<const float4*>(&pw[(size_t)(j0 + j) * (2 * DD) + k]);
#pragma unroll
        for (int b = 0; b < BB; b++) {
            float4 xv = *reinterpret_cast<const float4*>(&xs[b * DD + k]);
#pragma unroll
            for (int j = 0; j < 4; j++) {
                acc[j][b] = fmaf(wv[j].x, xv.x, acc[j][b]);
                acc[j][b] = fmaf(wv[j].y, xv.y, acc[j][b]);
                acc[j][b] = fmaf(wv[j].z, xv.z, acc[j][b]);
                acc[j][b] = fmaf(wv[j].w, xv.w, acc[j][b]);
            }
        }
    }
#pragma unroll
    for (int j = 0; j < 4; j++)
#pragma unroll
        for (int b = 0; b < BB; b++)
#pragma unroll
            for (int off = 16; off > 0; off >>= 1)
                acc[j][b] += __shfl_xor_sync(0xFFFFFFFFu, acc[j][b], off);
    if (lane == 0) {
#pragma unroll
        for (int j = 0; j < 4; j++) {
            float bb = pb[j0 + j];
#pragma unroll
            for (int b = 0; b < BB; b++)
                g_hb[b * DD + j0 + j] = acc[j][b] + bb;
        }
    }
}

// ---------------- segment metadata ------------------------------------------------
__global__ void meta_kernel(const int* __restrict__ bboxes,
                            float* __restrict__ att_mask_out) {
    __shared__ int counts[BB];
    __shared__ int offs[BB];
    int t = threadIdx.x;
    if (t < BB) counts[t] = 0;
    __syncthreads();
    int im = bboxes[t * 5];
    atomicAdd(&counts[im], 1);
    __syncthreads();
    if (t == 0) {
        int s = 0;
        for (int b = 0; b < BB; b++) { offs[b] = s; s += counts[b]; }
    }
    __syncthreads();
    g_pos[t] = t - offs[im];
    for (int i = t; i < BB * MAXB; i += NBOX) {
        int b = i / MAXB, m = i % MAXB;
        att_mask_out[i] = (m < counts[b]) ? 1.0f : 0.0f;
    }
}

// ---------------- convert operands to fp16 hi/lo -----------------------------------
#define CN1 (768*256)
#define CN2 (768*768)
#define CN3 (768*768)
#define CN4 (1024*256)
__global__ void conv_kernel(const float* __restrict__ m1w, const float* __restrict__ m2w,
                            const float* __restrict__ pw,  const float* __restrict__ feat) {
    const int TOT = CN1 + CN2 + CN3 + CN4;
    for (int i = blockIdx.x * blockDim.x + threadIdx.x; i < TOT;
         i += gridDim.x * blockDim.x) {
        float v; __half *oh, *ol; int o;
        if (i < CN1) { o = i; v = m1w[o]; oh = g_w1h; ol = g_w1l; }
        else if (i < CN1 + CN2) { o = i - CN1; v = m2w[o]; oh = g_w2h; ol = g_w2l; }
        else if (i < CN1 + CN2 + CN3) {
            o = i - CN1 - CN2;
            int col = o / 768, k = o - col * 768;
            v = pw[(size_t)col * (2 * DD) + DD + k];
            oh = g_wph; ol = g_wpl;
        } else {
            o = i - CN1 - CN2 - CN3;
            int n = o >> 8, k = o & 255;
            v = feat[(size_t)n * (DDETR + 1) + 1 + k];
            oh = g_feath; ol = g_featl;
        }
        __half h = __float2half_rn(v);
        oh[o] = h;
        ol[o] = __float2half_rn(v - __half2float(h));
    }
}

// ---------------- fp16 split GEMM: 256 thr, ldmatrix, cp.async double buffer -------
// 64x64 block tile, 8 warps of 32x16, k-chunks of 32 halves (16 half2).
// mode 0: fm1 = relu(feat @ m1w^T + m1b)   K=256
// mode 1: fm  = fm1 @ m2w^T + m2b          K=768
// mode 2: h   = fm @ pw2^T + hb[img]       K=768 -> scatter to vis_output
#define ARRW (64*20)            // words per operand array
__global__ __launch_bounds__(256) void hgemm(int mode,
        const float* __restrict__ bias,
        const int* __restrict__ bboxes,
        float* __restrict__ out_vis) {
    // [buf][arr: Ah,Al,Bh,Bl][row 64][k2 16 pad->20]
    __shared__ uint32_t S[2][4][64][20];
    __shared__ int simg[64];

    const int tid = threadIdx.x;
    const int bm = blockIdx.x, bn = blockIdx.y;
    const int wid = tid >> 5, lane = tid & 31, gid = lane >> 2, tig = lane & 3;
    const int wm = wid >> 2, wn = wid & 3;     // warp tile: rows wm*32, cols wn*16
    const int K = (mode == 0) ? 256 : 768;
    const int K2 = K >> 1;
    const int nch = K / 32;

    const __half *Ahp, *Alp, *Bhp, *Blp;
    if (mode == 0)      { Ahp = g_feath; Alp = g_featl; Bhp = g_w1h; Blp = g_w1l; }
    else if (mode == 1) { Ahp = g_fm1h;  Alp = g_fm1l;  Bhp = g_w2h; Blp = g_w2l; }
    else                { Ahp = g_fmh;   Alp = g_fml;   Bhp = g_wph; Blp = g_wpl; }

    const uint32_t* gsrc[4];
    gsrc[0] = (const uint32_t*)Ahp + (size_t)(bm * 64) * K2;
    gsrc[1] = (const uint32_t*)Alp + (size_t)(bm * 64) * K2;
    gsrc[2] = (const uint32_t*)Bhp + (size_t)(bn * 64) * K2;
    gsrc[3] = (const uint32_t*)Blp + (size_t)(bn * 64) * K2;

    if (mode == 2 && tid < 64) simg[tid] = bboxes[(bm * 64 + tid) * 5];

    const uint32_t sbase = smem_u32(&S[0][0][0][0]);

    // per-lane ldmatrix row/k2 offsets (byte offsets within an operand array)
    const int q = lane >> 3, lm = lane & 7;
    const uint32_t offA = (uint32_t)(((wm * 32 + lm + (q & 1) * 8) * 20
                                      + ((q >> 1) * 4)) * 4);
    const uint32_t offB = (uint32_t)(((wn * 16 + lm + (q >> 1) * 8) * 20
                                      + ((q & 1) * 4)) * 4);

    float acc[2][2][4];
#pragma unroll
    for (int mt = 0; mt < 2; mt++)
#pragma unroll
        for (int nt = 0; nt < 2; nt++)
#pragma unroll
            for (int x = 0; x < 4; x++) acc[mt][nt][x] = 0.f;

    // ---- issue loads for one chunk (1024 x 16B across 256 threads) ----
#define LOAD_CHUNK(ch, bf) do {                                              \
        int _kc2 = (ch) * 16;                                                \
        _Pragma("unroll")                                                    \
        for (int _i = 0; _i < 4; _i++) {                                     \
            int _id = tid + _i * 256;                                        \
            int _arr = _id >> 8;                                             \
            int _rem = _id & 255;                                            \
            int _row = _rem >> 2, _seg = _rem & 3;                           \
            const uint32_t* _gp = gsrc[_arr] + (size_t)_row * K2 + _kc2 + _seg * 4; \
            uint32_t _dst = sbase +                                          \
                ((((bf) * 4 + _arr) * 64 + _row) * 20 + _seg * 4) * 4;       \
            CP_ASYNC16(_dst, _gp);                                           \
        }                                                                    \
    } while (0)

    LOAD_CHUNK(0, 0);
    CP_COMMIT();

    for (int c = 0; c < nch; c++) {
        const int buf = c & 1;
        if (c + 1 < nch) {
            LOAD_CHUNK(c + 1, buf ^ 1);
            CP_COMMIT();
            CP_WAIT(1);
        } else {
            CP_WAIT(0);
        }
        __syncthreads();

#pragma unroll
        for (int p = 0; p < 3; p++) {
            const uint32_t baseA = sbase + (buf * 4 + (p == 1 ? 1 : 0)) * (ARRW * 4);
            const uint32_t baseB = sbase + (buf * 4 + (p == 2 ? 3 : 2)) * (ARRW * 4);
#pragma unroll
            for (int ks = 0; ks < 2; ks++) {
                uint32_t a0[4], a1[4], b[4];
                LDSM_X4(a0[0], a0[1], a0[2], a0[3], baseA + offA + ks * 32);
                LDSM_X4(a1[0], a1[1], a1[2], a1[3], baseA + offA + 1280 + ks * 32);
                LDSM_X4(b[0],  b[1],  b[2],  b[3],  baseB + offB + ks * 32);
#pragma unroll
                for (int nt = 0; nt < 2; nt++) {
                    asm volatile(
                        "mma.sync.aligned.m16n8k16.row.col.f32.f16.f16.f32 "
                        "{%0,%1,%2,%3}, {%4,%5,%6,%7}, {%8,%9}, {%0,%1,%2,%3};"
                        : "+f"(acc[0][nt][0]), "+f"(acc[0][nt][1]),
                          "+f"(acc[0][nt][2]), "+f"(acc[0][nt][3])
                        : "r"(a0[0]), "r"(a0[1]), "r"(a0[2]), "r"(a0[3]),
                          "r"(b[nt * 2]), "r"(b[nt * 2 + 1]));
                    asm volatile(
                        "mma.sync.aligned.m16n8k16.row.col.f32.f16.f16.f32 "
                        "{%0,%1,%2,%3}, {%4,%5,%6,%7}, {%8,%9}, {%0,%1,%2,%3};"
                        : "+f"(acc[1][nt][0]), "+f"(acc[1][nt][1]),
                          "+f"(acc[1][nt][2]), "+f"(acc[1][nt][3])
                        : "r"(a1[0]), "r"(a1[1]), "r"(a1[2]), "r"(a1[3]),
                          "r"(b[nt * 2]), "r"(b[nt * 2 + 1]));
                }
            }
        }
        __syncthreads();
    }
#undef LOAD_CHUNK

    const int col00 = bn * 64 + wn * 16;
    if (mode == 2) {
#pragma unroll
        for (int mt = 0; mt < 2; mt++) {
            int rl0 = wm * 32 + mt * 16 + gid, rl1 = rl0 + 8;
            int p0 = g_pos[bm * 64 + rl0], p1 = g_pos[bm * 64 + rl1];
            int im0 = simg[rl0], im1 = simg[rl1];
#pragma unroll
            for (int nt = 0; nt < 2; nt++) {
                int col = col00 + nt * 8 + tig * 2;
                if (p0 < MAXB) {
                    float* d = out_vis + ((size_t)im0 * MAXB + p0) * DD + col;
                    d[0] = acc[mt][nt][0] + g_hb[im0 * DD + col];
                    d[1] = acc[mt][nt][1] + g_hb[im0 * DD + col + 1];
                }
                if (p1 < MAXB) {
                    float* d = out_vis + ((size_t)im1 * MAXB + p1) * DD + col;
                    d[0] = acc[mt][nt][2] + g_hb[im1 * DD + col];
                    d[1] = acc[mt][nt][3] + g_hb[im1 * DD + col + 1];
                }
            }
        }
    } else {
        __half* oh = (mode == 0) ? g_fm1h : g_fmh;
        __half* ol = (mode == 0) ? g_fm1l : g_fml;
#pragma unroll
        for (int nt = 0; nt < 2; nt++) {
            int col = col00 + nt * 8 + tig * 2;
            float bv0 = bias[col], bv1 = bias[col + 1];
#pragma unroll
            for (int mt = 0; mt < 2; mt++) {
                int r = bm * 64 + wm * 32 + mt * 16 + gid;
                float v00 = acc[mt][nt][0] + bv0, v01 = acc[mt][nt][1] + bv1;
                float v10 = acc[mt][nt][2] + bv0, v11 = acc[mt][nt][3] + bv1;
                if (mode == 0) {
                    v00 = fmaxf(v00, 0.f); v01 = fmaxf(v01, 0.f);
                    v10 = fmaxf(v10, 0.f); v11 = fmaxf(v11, 0.f);
                }
                __half2 hp, lp;
                h2split(v00, &hp, &lp, v01);
                *(__half2*)&oh[(size_t)r * DD + col] = hp;
                *(__half2*)&ol[(size_t)r * DD + col] = lp;
                h2split(v10, &hp, &lp, v11);
                *(__half2*)&oh[(size_t)(r + 8) * DD + col] = hp;
                *(__half2*)&ol[(size_t)(r + 8) * DD + col] = lp;
            }
        }
    }
}

// ---------------- launch --------------------------------------------------------------
extern "C" void kernel_launch(void* const* d_in, const int* in_sizes, int n_in,
                              void* d_out, int out_size) {
    (void)in_sizes; (void)n_in; (void)out_size;
    const float* inputs   = (const float*)d_in[0];
    const int*   bboxes   = (const int*)  d_in[1];
    const float* features = (const float*)d_in[2];
    const float* t1w = (const float*)d_in[3],  *t1b = (const float*)d_in[4];
    const float* t2w = (const float*)d_in[5],  *t2b = (const float*)d_in[6];
    const float* d1w = (const float*)d_in[7],  *d1b = (const float*)d_in[8];
    const float* d2w = (const float*)d_in[9],  *d2b = (const float*)d_in[10];
    const float* m1w = (const float*)d_in[11], *m1b = (const float*)d_in[12];
    const float* m2w = (const float*)d_in[13], *m2b = (const float*)d_in[14];
    const float* pw  = (const float*)d_in[15], *pb  = (const float*)d_in[16];

    float* out      = (float*)d_out;
    float* out_vis  = out;
    float* out_mask = out + VIS_ELEMS;
    float* out_retx = out + VIS_ELEMS + MASK_ELEMS;

    conv_kernel<<<640, 256>>>(m1w, m2w, pw, features);             // 1
    mean_partial_kernel<<<BB * NC, 192>>>(inputs);                 // 2
    hgemm<<<dim3(16, 12), 256>>>(0, m1b, bboxes, nullptr);         // 3
    hgemm<<<dim3(16, 12), 256>>>(1, m2b, bboxes, nullptr);         // 4 <- profiled
    mean_final_kernel<<<12, 256>>>();                              // 5
    mlp_kernel<<<48, 256>>>(0, t1w, t1b, d1w, d1b, nullptr);       // 6
    mlp_kernel<<<48, 256>>>(1, t2w, t2b, d2w, d2b, out_retx);      // 7
    hb_kernel<<<24, 256>>>(pw, pb);                                // 8
    meta_kernel<<<1, NBOX>>>(bboxes, out_mask);                    // 9
    zero_vis_kernel<<<768, 256>>>((float4*)out_vis);               // 10
    hgemm<<<dim3(16, 12), 256>>>(2, nullptr, bboxes, out_vis);     // 11
}

// round 7
// speedup vs baseline: 1.0494x; 1.0494x over previous
#include <cuda_runtime.h>
#include <cuda_fp16.h>
#include <cstdint>

// Problem constants
#define BB 16
#define TT 4096
#define DD 768
#define NBOX 1024
#define MAXB 128
#define DDETR 256
#define VIS_ELEMS (BB*MAXB*DD)
#define MASK_ELEMS (BB*MAXB)
#define NC 64

// ---------------- scratch (device globals) -----------------------------------
__device__ __align__(16) float g_partial[BB*NC*DD];
__device__ __align__(16) float g_x[BB*DD];
__device__ __align__(16) float g_h1t[BB*DD];
__device__ __align__(16) float g_h1d[BB*DD];
__device__ __align__(16) float g_xt[BB*DD];
__device__ __align__(16) float g_hb[BB*DD];          // folded bias for gemm_h
__device__ int g_pos[NBOX];

// fp16 hi/lo operand arrays (row-major, k contiguous)
__device__ __align__(16) __half g_w1h[768*256],  g_w1l[768*256];
__device__ __align__(16) __half g_w2h[768*768],  g_w2l[768*768];
__device__ __align__(16) __half g_wph[768*768],  g_wpl[768*768];   // pw[:,768:]
__device__ __align__(16) __half g_feath[1024*256], g_featl[1024*256];
__device__ __align__(16) __half g_fm1h[1024*768],  g_fm1l[1024*768];
__device__ __align__(16) __half g_fmh[1024*768],   g_fml[1024*768];

// ---------------- helpers -------------------------------------------------------
__device__ __forceinline__ uint32_t smem_u32(const void* p) {
    uint32_t r;
    asm("{ .reg .u64 t; cvta.to.shared.u64 t, %1; cvt.u32.u64 %0, t; }"
        : "=r"(r) : "l"(p));
    return r;
}
#define CP_ASYNC16(dst, src) \
    asm volatile("cp.async.cg.shared.global [%0], [%1], 16;" \
                 :: "r"(dst), "l"(src) : "memory")
#define CP_COMMIT() asm volatile("cp.async.commit_group;" ::: "memory")
#define CP_WAIT(n)  asm volatile("cp.async.wait_group %0;" :: "n"(n) : "memory")

#define LDSM_X4(r0, r1, r2, r3, addr) \
    asm volatile("ldmatrix.sync.aligned.m8n8.x4.shared.b16 {%0,%1,%2,%3}, [%4];" \
                 : "=r"(r0), "=r"(r1), "=r"(r2), "=r"(r3) : "r"(addr))

#define MMA16816(acc, a0, a1, a2, a3, b0, b1) \
    asm volatile("mma.sync.aligned.m16n8k16.row.col.f32.f16.f16.f32 " \
                 "{%0,%1,%2,%3}, {%4,%5,%6,%7}, {%8,%9}, {%0,%1,%2,%3};" \
                 : "+f"((acc)[0]), "+f"((acc)[1]), "+f"((acc)[2]), "+f"((acc)[3]) \
                 : "r"(a0), "r"(a1), "r"(a2), "r"(a3), "r"(b0), "r"(b1))

__device__ __forceinline__ void h2split(float v, __half2* oh, __half2* ol,
                                        float v1) {
    __half h0 = __float2half_rn(v),  h1 = __float2half_rn(v1);
    __half l0 = __float2half_rn(v - __half2float(h0));
    __half l1 = __float2half_rn(v1 - __half2float(h1));
    *oh = __halves2half2(h0, h1);
    *ol = __halves2half2(l0, l1);
}

// ---------------- zero vis_output + segment metadata (merged) --------------------
__global__ void zero_meta_kernel(float4* __restrict__ out,
                                 const int* __restrict__ bboxes,
                                 float* __restrict__ att_mask_out) {
    const int n4 = VIS_ELEMS / 4;
    for (int i = blockIdx.x * blockDim.x + threadIdx.x; i < n4;
         i += gridDim.x * blockDim.x)
        out[i] = make_float4(0.f, 0.f, 0.f, 0.f);

    if (blockIdx.x == gridDim.x - 1) {
        __shared__ int counts[BB];
        __shared__ int offs[BB];
        int t = threadIdx.x;
        if (t < BB) counts[t] = 0;
        __syncthreads();
        for (int n = t; n < NBOX; n += blockDim.x)
            atomicAdd(&counts[bboxes[n * 5]], 1);
        __syncthreads();
        if (t == 0) {
            int s = 0;
            for (int b = 0; b < BB; b++) { offs[b] = s; s += counts[b]; }
        }
        __syncthreads();
        for (int n = t; n < NBOX; n += blockDim.x)
            g_pos[n] = n - offs[bboxes[n * 5]];
        for (int i = t; i < BB * MAXB; i += blockDim.x) {
            int b = i / MAXB, m = i % MAXB;
            att_mask_out[i] = (m < counts[b]) ? 1.0f : 0.0f;
        }
    }
}

// ---------------- mean pass 1 ----------------------------------------------------
__global__ void mean_partial_kernel(const float* __restrict__ in) {
    int b = blockIdx.x >> 6;
    int c = blockIdx.x & 63;
    const float4* p = reinterpret_cast<const float4*>(
        in + ((size_t)b * TT + (size_t)c * 64) * DD) + threadIdx.x;
    float4 acc = make_float4(0.f, 0.f, 0.f, 0.f);
    #pragma unroll 8
    for (int r = 0; r < 64; r++) {
        float4 v = p[(size_t)r * (DD / 4)];
        acc.x += v.x; acc.y += v.y; acc.z += v.z; acc.w += v.w;
    }
    reinterpret_cast<float4*>(g_partial + ((size_t)b * NC + c) * DD)[threadIdx.x] = acc;
}

// ---------------- mean pass 2 ----------------------------------------------------
__global__ void mean_final_kernel() {
    int i = blockIdx.x * blockDim.x + threadIdx.x;
    int b  = i / (DD / 4);
    int c4 = i % (DD / 4);
    const float4* p = reinterpret_cast<const float4*>(g_partial)
                      + (size_t)b * NC * (DD / 4) + c4;
    float4 acc = make_float4(0.f, 0.f, 0.f, 0.f);
    #pragma unroll 8
    for (int c = 0; c < NC; c++) {
        float4 v = p[(size_t)c * (DD / 4)];
        acc.x += v.x; acc.y += v.y; acc.z += v.z; acc.w += v.w;
    }
    const float s = 1.0f / (float)TT;
    acc.x *= s; acc.y *= s; acc.z *= s; acc.w *= s;
    reinterpret_cast<float4*>(g_x)[(size_t)b * (DD / 4) + c4] = acc;
}

// ---------------- small MLP: smem-staged x, 4 cols/warp ---------------------------
__global__ __launch_bounds__(256) void mlp_kernel(int layer,
        const float* __restrict__ wt, const float* __restrict__ bt,
        const float* __restrict__ wd, const float* __restrict__ bd,
        float* __restrict__ retx_out) {
    __shared__ __align__(16) float xs[BB * DD];
    int branch = blockIdx.x / 24;
    const float* in   = (layer == 0) ? g_x : (branch ? g_h1d : g_h1t);
    const float* w    = branch ? wd : wt;
    const float* bias = branch ? bd : bt;
    float* out        = (layer == 0) ? (branch ? g_h1d : g_h1t)
                                     : (branch ? retx_out : g_xt);
    {
        const float4* s = reinterpret_cast<const float4*>(in);
        float4* d = reinterpret_cast<float4*>(xs);
        for (int i = threadIdx.x; i < BB * DD / 4; i += 256) d[i] = s[i];
    }
    __syncthreads();

    int warp = threadIdx.x >> 5, lane = threadIdx.x & 31;
    int j0 = (blockIdx.x % 24) * 32 + warp * 4;
    float acc[4][BB];
#pragma unroll
    for (int j = 0; j < 4; j++)
#pragma unroll
        for (int b = 0; b < BB; b++) acc[j][b] = 0.f;

    for (int it = 0; it < DD / 128; it++) {
        int k = it * 128 + lane * 4;
        float4 wv[4];
#pragma unroll
        for (int j = 0; j < 4; j++)
            wv[j] = *reinterpret_cast<const float4*>(&w[(size_t)(j0 + j) * DD + k]);
#pragma unroll
        for (int b = 0; b < BB; b++) {
            float4 xv = *reinterpret_cast<const float4*>(&xs[b * DD + k]);
#pragma unroll
            for (int j = 0; j < 4; j++) {
                acc[j][b] = fmaf(wv[j].x, xv.x, acc[j][b]);
                acc[j][b] = fmaf(wv[j].y, xv.y, acc[j][b]);
                acc[j][b] = fmaf(wv[j].z, xv.z, acc[j][b]);
                acc[j][b] = fmaf(wv[j].w, xv.w, acc[j][b]);
            }
        }
    }
#pragma unroll
    for (int j = 0; j < 4; j++)
#pragma unroll
        for (int b = 0; b < BB; b++)
#pragma unroll
            for (int off = 16; off > 0; off >>= 1)
                acc[j][b] += __shfl_xor_sync(0xFFFFFFFFu, acc[j][b], off);
    if (lane == 0) {
#pragma unroll
        for (int j = 0; j < 4; j++) {
            float bb = bias[j0 + j];
#pragma unroll
            for (int b = 0; b < BB; b++) {
                float v = acc[j][b] + bb;
                if (layer == 0) v = fmaxf(v, 0.f);
                out[b * DD + j0 + j] = v;
            }
        }
    }
}

// ---------------- hb = pb + xt @ pw[:, :768]^T -----------------------------------
__global__ __launch_bounds__(256) void hb_kernel(const float* __restrict__ pw,
                                                 const float* __restrict__ pb) {
    __shared__ __align__(16) float xs[BB * DD];
    {
        const float4* s = reinterpret_cast<const float4*>(g_xt);
        float4* d = reinterpret_cast<float4*>(xs);
        for (int i = threadIdx.x; i < BB * DD / 4; i += 256) d[i] = s[i];
    }
    __syncthreads();
    int warp = threadIdx.x >> 5, lane = threadIdx.x & 31;
    int j0 = blockIdx.x * 32 + warp * 4;
    float acc[4][BB];
#pragma unroll
    for (int j = 0; j < 4; j++)
#pragma unroll
        for (int b = 0; b < BB; b++) acc[j][b] = 0.f;
    for (int it = 0; it < DD / 128; it++) {
        int k = it * 128 + lane * 4;
        float4 wv[4];
#pragma unroll
        for (int j = 0; j < 4; j++)
            wv[j] = *reinterpret_cast<const float4*>(&pw[(size_t)(j0 + j) * (2 * DD) + k]);
#pragma unroll
        for (int b = 0; b < BB; b++) {
            float4 xv = *reinterpret_cast<const float4*>(&xs[b * DD + k]);
#pragma unroll
            for (int j = 0; j < 4; j++) {
                acc[j][b] = fmaf(wv[j].x, xv.x, acc[j][b]);
                acc[j][b] = fmaf(wv[j].y, xv.y, acc[j][b]);
                acc[j][b] = fmaf(wv[j].z, xv.z, acc[j][b]);
                acc[j][b] = fmaf(wv[j].w, xv.w, acc[j][b]);
            }
        }
    }
#pragma unroll
    for (int j = 0; j < 4; j++)
#pragma unroll
        for (int b = 0; b < BB; b++)
#pragma unroll
            for (int off = 16; off > 0; off >>= 1)
                acc[j][b] += __shfl_xor_sync(0xFFFFFFFFu, acc[j][b], off);
    if (lane == 0) {
#pragma unroll
        for (int j = 0; j < 4; j++) {
            float bb = pb[j0 + j];
#pragma unroll
            for (int b = 0; b < BB; b++)
                g_hb[b * DD + j0 + j] = acc[j][b] + bb;
        }
    }
}

// ---------------- convert operands to fp16 hi/lo -----------------------------------
#define CN1 (768*256)
#define CN2 (768*768)
#define CN3 (768*768)
#define CN4 (1024*256)
__global__ void conv_kernel(const float* __restrict__ m1w, const float* __restrict__ m2w,
                            const float* __restrict__ pw,  const float* __restrict__ feat) {
    const int TOT = CN1 + CN2 + CN3 + CN4;
    for (int i = blockIdx.x * blockDim.x + threadIdx.x; i < TOT;
         i += gridDim.x * blockDim.x) {
        float v; __half *oh, *ol; int o;
        if (i < CN1) { o = i; v = m1w[o]; oh = g_w1h; ol = g_w1l; }
        else if (i < CN1 + CN2) { o = i - CN1; v = m2w[o]; oh = g_w2h; ol = g_w2l; }
        else if (i < CN1 + CN2 + CN3) {
            o = i - CN1 - CN2;
            int col = o / 768, k = o - col * 768;
            v = pw[(size_t)col * (2 * DD) + DD + k];
            oh = g_wph; ol = g_wpl;
        } else {
            o = i - CN1 - CN2 - CN3;
            int n = o >> 8, k = o & 255;
            v = feat[(size_t)n * (DDETR + 1) + 1 + k];
            oh = g_feath; ol = g_featl;
        }
        __half h = __float2half_rn(v);
        oh[o] = h;
        ol[o] = __float2half_rn(v - __half2float(h));
    }
}

// ---------------- fp16 split GEMM: 4-stage cp.async, 1 barrier/chunk ---------------
// 64x64 block tile, 256 thr (8 warps of 32x16), k-chunks of 32 halves.
// Per stage smem: 4 arrays [64][20] words = 20480 B. 4 stages = 81920 B (dynamic).
// mode 0: fm1 = relu(feat @ m1w^T + m1b)   K=256
// mode 1: fm  = fm1 @ m2w^T + m2b          K=768
// mode 2: h   = fm @ pw2^T + hb[img]       K=768 -> scatter to vis_output
#define NSTG 4
#define ARRB (64*20*4)          // bytes per operand array (5120)
#define STGB (4*ARRB)           // bytes per stage (20480)
#define GEMM_SMEM (NSTG*STGB)   // 81920
__global__ __launch_bounds__(256) void hgemm(int mode,
        const float* __restrict__ bias,
        const int* __restrict__ bboxes,
        float* __restrict__ out_vis) {
    extern __shared__ __align__(16) uint32_t S[];
    __shared__ int simg[64];

    const int tid = threadIdx.x;
    const int bm = blockIdx.x, bn = blockIdx.y;
    const int wid = tid >> 5, lane = tid & 31, gid = lane >> 2, tig = lane & 3;
    const int wm = wid >> 2, wn = wid & 3;     // warp tile: rows wm*32, cols wn*16
    const int K = (mode == 0) ? 256 : 768;
    const int K2 = K >> 1;
    const int nch = K / 32;

    const __half *Ahp, *Alp, *Bhp, *Blp;
    if (mode == 0)      { Ahp = g_feath; Alp = g_featl; Bhp = g_w1h; Blp = g_w1l; }
    else if (mode == 1) { Ahp = g_fm1h;  Alp = g_fm1l;  Bhp = g_w2h; Blp = g_w2l; }
    else                { Ahp = g_fmh;   Alp = g_fml;   Bhp = g_wph; Blp = g_wpl; }

    const uint32_t* gsrc[4];
    gsrc[0] = (const uint32_t*)Ahp + (size_t)(bm * 64) * K2;
    gsrc[1] = (const uint32_t*)Alp + (size_t)(bm * 64) * K2;
    gsrc[2] = (const uint32_t*)Bhp + (size_t)(bn * 64) * K2;
    gsrc[3] = (const uint32_t*)Blp + (size_t)(bn * 64) * K2;

    if (mode == 2 && tid < 64) simg[tid] = bboxes[(bm * 64 + tid) * 5];

    const uint32_t sbase = smem_u32(S);

    // per-lane ldmatrix offsets (byte offsets within an operand array)
    const int q = lane >> 3, lm = lane & 7;
    const uint32_t offA = (uint32_t)(((wm * 32 + lm + (q & 1) * 8) * 20
                                      + ((q >> 1) * 4)) * 4);
    const uint32_t offB = (uint32_t)(((wn * 16 + lm + (q >> 1) * 8) * 20
                                      + ((q & 1) * 4)) * 4);

    float acc[2][2][4];
#pragma unroll
    for (int mt = 0; mt < 2; mt++)
#pragma unroll
        for (int nt = 0; nt < 2; nt++)
#pragma unroll
            for (int x = 0; x < 4; x++) acc[mt][nt][x] = 0.f;

    // ---- issue loads for one chunk into one stage (1024 x 16B / 256 thr) ----
#define LOAD_CHUNK(ch, st) do {                                              \
        int _kc2 = (ch) * 16;                                                \
        _Pragma("unroll")                                                    \
        for (int _i = 0; _i < 4; _i++) {                                     \
            int _id = tid + _i * 256;                                        \
            int _arr = _id >> 8;                                             \
            int _rem = _id & 255;                                            \
            int _row = _rem >> 2, _seg = _rem & 3;                           \
            const uint32_t* _gp = gsrc[_arr] + (size_t)_row * K2 + _kc2 + _seg * 4; \
            uint32_t _dst = sbase + (st) * STGB + _arr * ARRB                \
                            + (_row * 20 + _seg * 4) * 4;                    \
            CP_ASYNC16(_dst, _gp);                                           \
        }                                                                    \
    } while (0)

    // prologue: prefetch NSTG-1 chunks
#pragma unroll
    for (int s = 0; s < NSTG - 1; s++) {
        LOAD_CHUNK(s, s);
        CP_COMMIT();
    }

    for (int c = 0; c < nch; c++) {
        CP_WAIT(NSTG - 2);        // chunk c resident
        __syncthreads();          // visibility + slot-reuse safety
        if (c + NSTG - 1 < nch) {
            LOAD_CHUNK(c + NSTG - 1, (c + NSTG - 1) & (NSTG - 1));
        }
        CP_COMMIT();              // keep group count uniform

        const uint32_t stb = sbase + (c & (NSTG - 1)) * STGB;
#pragma unroll
        for (int ks = 0; ks < 2; ks++) {
            uint32_t ah0[4], ah1[4], al0[4], al1[4], bh[4], bl[4];
            LDSM_X4(ah0[0], ah0[1], ah0[2], ah0[3], stb + offA + ks * 32);
            LDSM_X4(ah1[0], ah1[1], ah1[2], ah1[3], stb + offA + 1280 + ks * 32);
            LDSM_X4(al0[0], al0[1], al0[2], al0[3], stb + ARRB + offA + ks * 32);
            LDSM_X4(al1[0], al1[1], al1[2], al1[3], stb + ARRB + offA + 1280 + ks * 32);
            LDSM_X4(bh[0],  bh[1],  bh[2],  bh[3],  stb + 2 * ARRB + offB + ks * 32);
            LDSM_X4(bl[0],  bl[1],  bl[2],  bl[3],  stb + 3 * ARRB + offB + ks * 32);
#pragma unroll
            for (int nt = 0; nt < 2; nt++) {
                uint32_t b0 = bh[nt * 2], b1 = bh[nt * 2 + 1];
                uint32_t c0 = bl[nt * 2], c1 = bl[nt * 2 + 1];
                MMA16816(acc[0][nt], ah0[0], ah0[1], ah0[2], ah0[3], b0, b1);
                MMA16816(acc[1][nt], ah1[0], ah1[1], ah1[2], ah1[3], b0, b1);
                MMA16816(acc[0][nt], al0[0], al0[1], al0[2], al0[3], b0, b1);
                MMA16816(acc[1][nt], al1[0], al1[1], al1[2], al1[3], b0, b1);
                MMA16816(acc[0][nt], ah0[0], ah0[1], ah0[2], ah0[3], c0, c1);
                MMA16816(acc[1][nt], ah1[0], ah1[1], ah1[2], ah1[3], c0, c1);
            }
        }
    }
#undef LOAD_CHUNK

    const int col00 = bn * 64 + wn * 16;
    if (mode == 2) {
#pragma unroll
        for (int mt = 0; mt < 2; mt++) {
            int rl0 = wm * 32 + mt * 16 + gid, rl1 = rl0 + 8;
            int p0 = g_pos[bm * 64 + rl0], p1 = g_pos[bm * 64 + rl1];
            int im0 = simg[rl0], im1 = simg[rl1];
#pragma unroll
            for (int nt = 0; nt < 2; nt++) {
                int col = col00 + nt * 8 + tig * 2;
                if (p0 < MAXB) {
                    float* d = out_vis + ((size_t)im0 * MAXB + p0) * DD + col;
                    d[0] = acc[mt][nt][0] + g_hb[im0 * DD + col];
                    d[1] = acc[mt][nt][1] + g_hb[im0 * DD + col + 1];
                }
                if (p1 < MAXB) {
                    float* d = out_vis + ((size_t)im1 * MAXB + p1) * DD + col;
                    d[0] = acc[mt][nt][2] + g_hb[im1 * DD + col];
                    d[1] = acc[mt][nt][3] + g_hb[im1 * DD + col + 1];
                }
            }
        }
    } else {
        __half* oh = (mode == 0) ? g_fm1h : g_fmh;
        __half* ol = (mode == 0) ? g_fm1l : g_fml;
#pragma unroll
        for (int nt = 0; nt < 2; nt++) {
            int col = col00 + nt * 8 + tig * 2;
            float bv0 = bias[col], bv1 = bias[col + 1];
#pragma unroll
            for (int mt = 0; mt < 2; mt++) {
                int r = bm * 64 + wm * 32 + mt * 16 + gid;
                float v00 = acc[mt][nt][0] + bv0, v01 = acc[mt][nt][1] + bv1;
                float v10 = acc[mt][nt][2] + bv0, v11 = acc[mt][nt][3] + bv1;
                if (mode == 0) {
                    v00 = fmaxf(v00, 0.f); v01 = fmaxf(v01, 0.f);
                    v10 = fmaxf(v10, 0.f); v11 = fmaxf(v11, 0.f);
                }
                __half2 hp, lp;
                h2split(v00, &hp, &lp, v01);
                *(__half2*)&oh[(size_t)r * DD + col] = hp;
                *(__half2*)&ol[(size_t)r * DD + col] = lp;
                h2split(v10, &hp, &lp, v11);
                *(__half2*)&oh[(size_t)(r + 8) * DD + col] = hp;
                *(__half2*)&ol[(size_t)(r + 8) * DD + col] = lp;
            }
        }
    }
}

// ---------------- launch --------------------------------------------------------------
extern "C" void kernel_launch(void* const* d_in, const int* in_sizes, int n_in,
                              void* d_out, int out_size) {
    (void)in_sizes; (void)n_in; (void)out_size;
    const float* inputs   = (const float*)d_in[0];
    const int*   bboxes   = (const int*)  d_in[1];
    const float* features = (const float*)d_in[2];
    const float* t1w = (const float*)d_in[3],  *t1b = (const float*)d_in[4];
    const float* t2w = (const float*)d_in[5],  *t2b = (const float*)d_in[6];
    const float* d1w = (const float*)d_in[7],  *d1b = (const float*)d_in[8];
    const float* d2w = (const float*)d_in[9],  *d2b = (const float*)d_in[10];
    const float* m1w = (const float*)d_in[11], *m1b = (const float*)d_in[12];
    const float* m2w = (const float*)d_in[13], *m2b = (const float*)d_in[14];
    const float* pw  = (const float*)d_in[15], *pb  = (const float*)d_in[16];

    float* out      = (float*)d_out;
    float* out_vis  = out;
    float* out_mask = out + VIS_ELEMS;
    float* out_retx = out + VIS_ELEMS + MASK_ELEMS;

    cudaFuncSetAttribute(hgemm, cudaFuncAttributeMaxDynamicSharedMemorySize,
                         GEMM_SMEM);

    conv_kernel<<<640, 256>>>(m1w, m2w, pw, features);                  // 1
    mean_partial_kernel<<<BB * NC, 192>>>(inputs);                      // 2
    hgemm<<<dim3(16, 12), 256, GEMM_SMEM>>>(0, m1b, bboxes, nullptr);   // 3
    hgemm<<<dim3(16, 12), 256, GEMM_SMEM>>>(1, m2b, bboxes, nullptr);   // 4 <- profiled
    mean_final_kernel<<<12, 256>>>();                                   // 5
    mlp_kernel<<<48, 256>>>(0, t1w, t1b, d1w, d1b, nullptr);            // 6
    mlp_kernel<<<48, 256>>>(1, t2w, t2b, d2w, d2b, out_retx);           // 7
    hb_kernel<<<24, 256>>>(pw, pb);                                     // 8
    zero_meta_kernel<<<768, 256>>>((float4*)out_vis, bboxes, out_mask); // 9
    hgemm<<<dim3(16, 12), 256, GEMM_SMEM>>>(2, nullptr, bboxes, out_vis); // 10
}

// round 8
// speedup vs baseline: 1.3867x; 1.3214x over previous
#include <cuda_runtime.h>
#include <cuda_fp16.h>
#include <cstdint>

// Problem constants
#define BB 16
#define TT 4096
#define DD 768
#define NBOX 1024
#define MAXB 128
#define DDETR 256
#define VIS_ELEMS (BB*MAXB*DD)
#define MASK_ELEMS (BB*MAXB)
#define NC 64

// ---------------- scratch (device globals) -----------------------------------
__device__ __align__(16) float g_partial[BB*NC*DD];
__device__ __align__(16) float g_x[BB*DD];
__device__ __align__(16) float g_h1t[BB*DD];
__device__ __align__(16) float g_h1d[BB*DD];
__device__ __align__(16) float g_xt[BB*DD];
__device__ __align__(16) float g_hb[BB*DD];          // folded bias for gemm_h
__device__ int g_pos[NBOX];

// fp16 hi/lo operand arrays (row-major, k contiguous)
__device__ __align__(16) __half g_w1h[768*256],  g_w1l[768*256];
__device__ __align__(16) __half g_w2h[768*768],  g_w2l[768*768];
__device__ __align__(16) __half g_wph[768*768],  g_wpl[768*768];   // pw[:,768:]
__device__ __align__(16) __half g_feath[1024*256], g_featl[1024*256];
__device__ __align__(16) __half g_fm1h[1024*768],  g_fm1l[1024*768];
__device__ __align__(16) __half g_fmh[1024*768],   g_fml[1024*768];

// ---------------- helpers -------------------------------------------------------
__device__ __forceinline__ uint32_t smem_u32(const void* p) {
    uint32_t r;
    asm("{ .reg .u64 t; cvta.to.shared.u64 t, %1; cvt.u32.u64 %0, t; }"
        : "=r"(r) : "l"(p));
    return r;
}
#define CP_ASYNC16(dst, src) \
    asm volatile("cp.async.cg.shared.global [%0], [%1], 16;" \
                 :: "r"(dst), "l"(src) : "memory")
#define CP_COMMIT() asm volatile("cp.async.commit_group;" ::: "memory")
#define CP_WAIT(n)  asm volatile("cp.async.wait_group %0;" :: "n"(n) : "memory")

#define LDSM_X4(r0, r1, r2, r3, addr) \
    asm volatile("ldmatrix.sync.aligned.m8n8.x4.shared.b16 {%0,%1,%2,%3}, [%4];" \
                 : "=r"(r0), "=r"(r1), "=r"(r2), "=r"(r3) : "r"(addr))

#define MMA16816(acc, a0, a1, a2, a3, b0, b1) \
    asm volatile("mma.sync.aligned.m16n8k16.row.col.f32.f16.f16.f32 " \
                 "{%0,%1,%2,%3}, {%4,%5,%6,%7}, {%8,%9}, {%0,%1,%2,%3};" \
                 : "+f"((acc)[0]), "+f"((acc)[1]), "+f"((acc)[2]), "+f"((acc)[3]) \
                 : "r"(a0), "r"(a1), "r"(a2), "r"(a3), "r"(b0), "r"(b1))

__device__ __forceinline__ void h2split(float v, __half2* oh, __half2* ol,
                                        float v1) {
    __half h0 = __float2half_rn(v),  h1 = __float2half_rn(v1);
    __half l0 = __float2half_rn(v - __half2float(h0));
    __half l1 = __float2half_rn(v1 - __half2float(h1));
    *oh = __halves2half2(h0, h1);
    *ol = __halves2half2(l0, l1);
}

// ---------------- zero vis_output + segment metadata (merged) --------------------
__global__ void zero_meta_kernel(float4* __restrict__ out,
                                 const int* __restrict__ bboxes,
                                 float* __restrict__ att_mask_out) {
    const int n4 = VIS_ELEMS / 4;
    for (int i = blockIdx.x * blockDim.x + threadIdx.x; i < n4;
         i += gridDim.x * blockDim.x)
        out[i] = make_float4(0.f, 0.f, 0.f, 0.f);

    if (blockIdx.x == gridDim.x - 1) {
        __shared__ int counts[BB];
        __shared__ int offs[BB];
        int t = threadIdx.x;
        if (t < BB) counts[t] = 0;
        __syncthreads();
        for (int n = t; n < NBOX; n += blockDim.x)
            atomicAdd(&counts[bboxes[n * 5]], 1);
        __syncthreads();
        if (t == 0) {
            int s = 0;
            for (int b = 0; b < BB; b++) { offs[b] = s; s += counts[b]; }
        }
        __syncthreads();
        for (int n = t; n < NBOX; n += blockDim.x)
            g_pos[n] = n - offs[bboxes[n * 5]];
        for (int i = t; i < BB * MAXB; i += blockDim.x) {
            int b = i / MAXB, m = i % MAXB;
            att_mask_out[i] = (m < counts[b]) ? 1.0f : 0.0f;
        }
    }
}

// ---------------- mean pass 1 ----------------------------------------------------
__global__ void mean_partial_kernel(const float* __restrict__ in) {
    int b = blockIdx.x >> 6;
    int c = blockIdx.x & 63;
    const float4* p = reinterpret_cast<const float4*>(
        in + ((size_t)b * TT + (size_t)c * 64) * DD) + threadIdx.x;
    float4 acc = make_float4(0.f, 0.f, 0.f, 0.f);
    #pragma unroll 8
    for (int r = 0; r < 64; r++) {
        float4 v = p[(size_t)r * (DD / 4)];
        acc.x += v.x; acc.y += v.y; acc.z += v.z; acc.w += v.w;
    }
    reinterpret_cast<float4*>(g_partial + ((size_t)b * NC + c) * DD)[threadIdx.x] = acc;
}

// ---------------- mean pass 2 ----------------------------------------------------
__global__ void mean_final_kernel() {
    int i = blockIdx.x * blockDim.x + threadIdx.x;
    int b  = i / (DD / 4);
    int c4 = i % (DD / 4);
    const float4* p = reinterpret_cast<const float4*>(g_partial)
                      + (size_t)b * NC * (DD / 4) + c4;
    float4 acc = make_float4(0.f, 0.f, 0.f, 0.f);
    #pragma unroll 8
    for (int c = 0; c < NC; c++) {
        float4 v = p[(size_t)c * (DD / 4)];
        acc.x += v.x; acc.y += v.y; acc.z += v.z; acc.w += v.w;
    }
    const float s = 1.0f / (float)TT;
    acc.x *= s; acc.y *= s; acc.z *= s; acc.w *= s;
    reinterpret_cast<float4*>(g_x)[(size_t)b * (DD / 4) + c4] = acc;
}

// ---------------- small MLP: smem-staged x, 4 cols/warp ---------------------------
__global__ __launch_bounds__(256) void mlp_kernel(int layer,
        const float* __restrict__ wt, const float* __restrict__ bt,
        const float* __restrict__ wd, const float* __restrict__ bd,
        float* __restrict__ retx_out) {
    __shared__ __align__(16) float xs[BB * DD];
    int branch = blockIdx.x / 24;
    const float* in   = (layer == 0) ? g_x : (branch ? g_h1d : g_h1t);
    const float* w    = branch ? wd : wt;
    const float* bias = branch ? bd : bt;
    float* out        = (layer == 0) ? (branch ? g_h1d : g_h1t)
                                     : (branch ? retx_out : g_xt);
    {
        const float4* s = reinterpret_cast<const float4*>(in);
        float4* d = reinterpret_cast<float4*>(xs);
        for (int i = threadIdx.x; i < BB * DD / 4; i += 256) d[i] = s[i];
    }
    __syncthreads();

    int warp = threadIdx.x >> 5, lane = threadIdx.x & 31;
    int j0 = (blockIdx.x % 24) * 32 + warp * 4;
    float acc[4][BB];
#pragma unroll
    for (int j = 0; j < 4; j++)
#pragma unroll
        for (int b = 0; b < BB; b++) acc[j][b] = 0.f;

    for (int it = 0; it < DD / 128; it++) {
        int k = it * 128 + lane * 4;
        float4 wv[4];
#pragma unroll
        for (int j = 0; j < 4; j++)
            wv[j] = *reinterpret_cast<const float4*>(&w[(size_t)(j0 + j) * DD + k]);
#pragma unroll
        for (int b = 0; b < BB; b++) {
            float4 xv = *reinterpret_cast<const float4*>(&xs[b * DD + k]);
#pragma unroll
            for (int j = 0; j < 4; j++) {
                acc[j][b] = fmaf(wv[j].x, xv.x, acc[j][b]);
                acc[j][b] = fmaf(wv[j].y, xv.y, acc[j][b]);
                acc[j][b] = fmaf(wv[j].z, xv.z, acc[j][b]);
                acc[j][b] = fmaf(wv[j].w, xv.w, acc[j][b]);
            }
        }
    }
#pragma unroll
    for (int j = 0; j < 4; j++)
#pragma unroll
        for (int b = 0; b < BB; b++)
#pragma unroll
            for (int off = 16; off > 0; off >>= 1)
                acc[j][b] += __shfl_xor_sync(0xFFFFFFFFu, acc[j][b], off);
    if (lane == 0) {
#pragma unroll
        for (int j = 0; j < 4; j++) {
            float bb = bias[j0 + j];
#pragma unroll
            for (int b = 0; b < BB; b++) {
                float v = acc[j][b] + bb;
                if (layer == 0) v = fmaxf(v, 0.f);
                out[b * DD + j0 + j] = v;
            }
        }
    }
}

// ---------------- hb = pb + xt @ pw[:, :768]^T -----------------------------------
__global__ __launch_bounds__(256) void hb_kernel(const float* __restrict__ pw,
                                                 const float* __restrict__ pb) {
    __shared__ __align__(16) float xs[BB * DD];
    {
        const float4* s = reinterpret_cast<const float4*>(g_xt);
        float4* d = reinterpret_cast<float4*>(xs);
        for (int i = threadIdx.x; i < BB * DD / 4; i += 256) d[i] = s[i];
    }
    __syncthreads();
    int warp = threadIdx.x >> 5, lane = threadIdx.x & 31;
    int j0 = blockIdx.x * 32 + warp * 4;
    float acc[4][BB];
#pragma unroll
    for (int j = 0; j < 4; j++)
#pragma unroll
        for (int b = 0; b < BB; b++) acc[j][b] = 0.f;
    for (int it = 0; it < DD / 128; it++) {
        int k = it * 128 + lane * 4;
        float4 wv[4];
#pragma unroll
        for (int j = 0; j < 4; j++)
            wv[j] = *reinterpret_cast<const float4*>(&pw[(size_t)(j0 + j) * (2 * DD) + k]);
#pragma unroll
        for (int b = 0; b < BB; b++) {
            float4 xv = *reinterpret_cast<const float4*>(&xs[b * DD + k]);
#pragma unroll
            for (int j = 0; j < 4; j++) {
                acc[j][b] = fmaf(wv[j].x, xv.x, acc[j][b]);
                acc[j][b] = fmaf(wv[j].y, xv.y, acc[j][b]);
                acc[j][b] = fmaf(wv[j].z, xv.z, acc[j][b]);
                acc[j][b] = fmaf(wv[j].w, xv.w, acc[j][b]);
            }
        }
    }
#pragma unroll
    for (int j = 0; j < 4; j++)
#pragma unroll
        for (int b = 0; b < BB; b++)
#pragma unroll
            for (int off = 16; off > 0; off >>= 1)
                acc[j][b] += __shfl_xor_sync(0xFFFFFFFFu, acc[j][b], off);
    if (lane == 0) {
#pragma unroll
        for (int j = 0; j < 4; j++) {
            float bb = pb[j0 + j];
#pragma unroll
            for (int b = 0; b < BB; b++)
                g_hb[b * DD + j0 + j] = acc[j][b] + bb;
        }
    }
}

// ---------------- convert operands to fp16 hi/lo -----------------------------------
#define CN1 (768*256)
#define CN2 (768*768)
#define CN3 (768*768)
#define CN4 (1024*256)
__global__ void conv_kernel(const float* __restrict__ m1w, const float* __restrict__ m2w,
                            const float* __restrict__ pw,  const float* __restrict__ feat) {
    const int TOT = CN1 + CN2 + CN3 + CN4;
    for (int i = blockIdx.x * blockDim.x + threadIdx.x; i < TOT;
         i += gridDim.x * blockDim.x) {
        float v; __half *oh, *ol; int o;
        if (i < CN1) { o = i; v = m1w[o]; oh = g_w1h; ol = g_w1l; }
        else if (i < CN1 + CN2) { o = i - CN1; v = m2w[o]; oh = g_w2h; ol = g_w2l; }
        else if (i < CN1 + CN2 + CN3) {
            o = i - CN1 - CN2;
            int col = o / 768, k = o - col * 768;
            v = pw[(size_t)col * (2 * DD) + DD + k];
            oh = g_wph; ol = g_wpl;
        } else {
            o = i - CN1 - CN2 - CN3;
            int n = o >> 8, k = o & 255;
            v = feat[(size_t)n * (DDETR + 1) + 1 + k];
            oh = g_feath; ol = g_featl;
        }
        __half h = __float2half_rn(v);
        oh[o] = h;
        ol[o] = __float2half_rn(v - __half2float(h));
    }
}

// ---------------- fp16 split GEMM: 4-stage cp.async, 1 barrier/chunk ---------------
#define NSTG 4
#define ARRB (64*20*4)          // bytes per operand array (5120)
#define STGB (4*ARRB)           // bytes per stage (20480)
#define GEMM_SMEM (NSTG*STGB)   // 81920
__global__ __launch_bounds__(256) void hgemm(int mode,
        const float* __restrict__ bias,
        const int* __restrict__ bboxes,
        float* __restrict__ out_vis) {
    extern __shared__ __align__(16) uint32_t S[];
    __shared__ int simg[64];

    const int tid = threadIdx.x;
    const int bm = blockIdx.x, bn = blockIdx.y;
    const int wid = tid >> 5, lane = tid & 31, gid = lane >> 2, tig = lane & 3;
    const int wm = wid >> 2, wn = wid & 3;     // warp tile: rows wm*32, cols wn*16
    const int K = (mode == 0) ? 256 : 768;
    const int K2 = K >> 1;
    const int nch = K / 32;

    const __half *Ahp, *Alp, *Bhp, *Blp;
    if (mode == 0)      { Ahp = g_feath; Alp = g_featl; Bhp = g_w1h; Blp = g_w1l; }
    else if (mode == 1) { Ahp = g_fm1h;  Alp = g_fm1l;  Bhp = g_w2h; Blp = g_w2l; }
    else                { Ahp = g_fmh;   Alp = g_fml;   Bhp = g_wph; Blp = g_wpl; }

    const uint32_t* gsrc[4];
    gsrc[0] = (const uint32_t*)Ahp + (size_t)(bm * 64) * K2;
    gsrc[1] = (const uint32_t*)Alp + (size_t)(bm * 64) * K2;
    gsrc[2] = (const uint32_t*)Bhp + (size_t)(bn * 64) * K2;
    gsrc[3] = (const uint32_t*)Blp + (size_t)(bn * 64) * K2;

    if (mode == 2 && tid < 64) simg[tid] = bboxes[(bm * 64 + tid) * 5];

    const uint32_t sbase = smem_u32(S);

    const int q = lane >> 3, lm = lane & 7;
    const uint32_t offA = (uint32_t)(((wm * 32 + lm + (q & 1) * 8) * 20
                                      + ((q >> 1) * 4)) * 4);
    const uint32_t offB = (uint32_t)(((wn * 16 + lm + (q >> 1) * 8) * 20
                                      + ((q & 1) * 4)) * 4);

    float acc[2][2][4];
#pragma unroll
    for (int mt = 0; mt < 2; mt++)
#pragma unroll
        for (int nt = 0; nt < 2; nt++)
#pragma unroll
            for (int x = 0; x < 4; x++) acc[mt][nt][x] = 0.f;

#define LOAD_CHUNK(ch, st) do {                                              \
        int _kc2 = (ch) * 16;                                                \
        _Pragma("unroll")                                                    \
        for (int _i = 0; _i < 4; _i++) {                                     \
            int _id = tid + _i * 256;                                        \
            int _arr = _id >> 8;                                             \
            int _rem = _id & 255;                                            \
            int _row = _rem >> 2, _seg = _rem & 3;                           \
            const uint32_t* _gp = gsrc[_arr] + (size_t)_row * K2 + _kc2 + _seg * 4; \
            uint32_t _dst = sbase + (st) * STGB + _arr * ARRB                \
                            + (_row * 20 + _seg * 4) * 4;                    \
            CP_ASYNC16(_dst, _gp);                                           \
        }                                                                    \
    } while (0)

#pragma unroll
    for (int s = 0; s < NSTG - 1; s++) {
        LOAD_CHUNK(s, s);
        CP_COMMIT();
    }

    for (int c = 0; c < nch; c++) {
        CP_WAIT(NSTG - 2);
        __syncthreads();
        if (c + NSTG - 1 < nch) {
            LOAD_CHUNK(c + NSTG - 1, (c + NSTG - 1) & (NSTG - 1));
        }
        CP_COMMIT();

        const uint32_t stb = sbase + (c & (NSTG - 1)) * STGB;
#pragma unroll
        for (int ks = 0; ks < 2; ks++) {
            uint32_t ah0[4], ah1[4], al0[4], al1[4], bh[4], bl[4];
            LDSM_X4(ah0[0], ah0[1], ah0[2], ah0[3], stb + offA + ks * 32);
            LDSM_X4(ah1[0], ah1[1], ah1[2], ah1[3], stb + offA + 1280 + ks * 32);
            LDSM_X4(al0[0], al0[1], al0[2], al0[3], stb + ARRB + offA + ks * 32);
            LDSM_X4(al1[0], al1[1], al1[2], al1[3], stb + ARRB + offA + 1280 + ks * 32);
            LDSM_X4(bh[0],  bh[1],  bh[2],  bh[3],  stb + 2 * ARRB + offB + ks * 32);
            LDSM_X4(bl[0],  bl[1],  bl[2],  bl[3],  stb + 3 * ARRB + offB + ks * 32);
#pragma unroll
            for (int nt = 0; nt < 2; nt++) {
                uint32_t b0 = bh[nt * 2], b1 = bh[nt * 2 + 1];
                uint32_t c0 = bl[nt * 2], c1 = bl[nt * 2 + 1];
                MMA16816(acc[0][nt], ah0[0], ah0[1], ah0[2], ah0[3], b0, b1);
                MMA16816(acc[1][nt], ah1[0], ah1[1], ah1[2], ah1[3], b0, b1);
                MMA16816(acc[0][nt], al0[0], al0[1], al0[2], al0[3], b0, b1);
                MMA16816(acc[1][nt], al1[0], al1[1], al1[2], al1[3], b0, b1);
                MMA16816(acc[0][nt], ah0[0], ah0[1], ah0[2], ah0[3], c0, c1);
                MMA16816(acc[1][nt], ah1[0], ah1[1], ah1[2], ah1[3], c0, c1);
            }
        }
    }
#undef LOAD_CHUNK

    const int col00 = bn * 64 + wn * 16;
    if (mode == 2) {
#pragma unroll
        for (int mt = 0; mt < 2; mt++) {
            int rl0 = wm * 32 + mt * 16 + gid, rl1 = rl0 + 8;
            int p0 = g_pos[bm * 64 + rl0], p1 = g_pos[bm * 64 + rl1];
            int im0 = simg[rl0], im1 = simg[rl1];
#pragma unroll
            for (int nt = 0; nt < 2; nt++) {
                int col = col00 + nt * 8 + tig * 2;
                if (p0 < MAXB) {
                    float* d = out_vis + ((size_t)im0 * MAXB + p0) * DD + col;
                    d[0] = acc[mt][nt][0] + g_hb[im0 * DD + col];
                    d[1] = acc[mt][nt][1] + g_hb[im0 * DD + col + 1];
                }
                if (p1 < MAXB) {
                    float* d = out_vis + ((size_t)im1 * MAXB + p1) * DD + col;
                    d[0] = acc[mt][nt][2] + g_hb[im1 * DD + col];
                    d[1] = acc[mt][nt][3] + g_hb[im1 * DD + col + 1];
                }
            }
        }
    } else {
        __half* oh = (mode == 0) ? g_fm1h : g_fmh;
        __half* ol = (mode == 0) ? g_fm1l : g_fml;
#pragma unroll
        for (int nt = 0; nt < 2; nt++) {
            int col = col00 + nt * 8 + tig * 2;
            float bv0 = bias[col], bv1 = bias[col + 1];
#pragma unroll
            for (int mt = 0; mt < 2; mt++) {
                int r = bm * 64 + wm * 32 + mt * 16 + gid;
                float v00 = acc[mt][nt][0] + bv0, v01 = acc[mt][nt][1] + bv1;
                float v10 = acc[mt][nt][2] + bv0, v11 = acc[mt][nt][3] + bv1;
                if (mode == 0) {
                    v00 = fmaxf(v00, 0.f); v01 = fmaxf(v01, 0.f);
                    v10 = fmaxf(v10, 0.f); v11 = fmaxf(v11, 0.f);
                }
                __half2 hp, lp;
                h2split(v00, &hp, &lp, v01);
                *(__half2*)&oh[(size_t)r * DD + col] = hp;
                *(__half2*)&ol[(size_t)r * DD + col] = lp;
                h2split(v10, &hp, &lp, v11);
                *(__half2*)&oh[(size_t)(r + 8) * DD + col] = hp;
                *(__half2*)&ol[(size_t)(r + 8) * DD + col] = lp;
            }
        }
    }
}

// ---------------- launch: forked graph (A: GEMM chain, B: mean/MLP chain) ----------
extern "C" void kernel_launch(void* const* d_in, const int* in_sizes, int n_in,
                              void* d_out, int out_size) {
    (void)in_sizes; (void)n_in; (void)out_size;
    const float* inputs   = (const float*)d_in[0];
    const int*   bboxes   = (const int*)  d_in[1];
    const float* features = (const float*)d_in[2];
    const float* t1w = (const float*)d_in[3],  *t1b = (const float*)d_in[4];
    const float* t2w = (const float*)d_in[5],  *t2b = (const float*)d_in[6];
    const float* d1w = (const float*)d_in[7],  *d1b = (const float*)d_in[8];
    const float* d2w = (const float*)d_in[9],  *d2b = (const float*)d_in[10];
    const float* m1w = (const float*)d_in[11], *m1b = (const float*)d_in[12];
    const float* m2w = (const float*)d_in[13], *m2b = (const float*)d_in[14];
    const float* pw  = (const float*)d_in[15], *pb  = (const float*)d_in[16];

    float* out      = (float*)d_out;
    float* out_vis  = out;
    float* out_mask = out + VIS_ELEMS;
    float* out_retx = out + VIS_ELEMS + MASK_ELEMS;

    cudaFuncSetAttribute(hgemm, cudaFuncAttributeMaxDynamicSharedMemorySize,
                         GEMM_SMEM);

    static cudaStream_t s2 = nullptr;
    static cudaEvent_t eFork = nullptr, eJoin = nullptr;
    if (s2 == nullptr) {
        cudaStreamCreateWithFlags(&s2, cudaStreamNonBlocking);
        cudaEventCreateWithFlags(&eFork, cudaEventDisableTiming);
        cudaEventCreateWithFlags(&eJoin, cudaEventDisableTiming);
    }

    // fork
    cudaEventRecord(eFork, 0);
    cudaStreamWaitEvent(s2, eFork, 0);

    // ---- branch B (stream s2): mean -> MLPs -> zero+meta ----
    mean_partial_kernel<<<BB * NC, 192, 0, s2>>>(inputs);
    mean_final_kernel<<<12, 256, 0, s2>>>();
    mlp_kernel<<<48, 256, 0, s2>>>(0, t1w, t1b, d1w, d1b, nullptr);
    mlp_kernel<<<48, 256, 0, s2>>>(1, t2w, t2b, d2w, d2b, out_retx);
    zero_meta_kernel<<<768, 256, 0, s2>>>((float4*)out_vis, bboxes, out_mask);
    cudaEventRecord(eJoin, s2);

    // ---- branch A (default stream): conv -> gemm0 -> gemm1 ----
    conv_kernel<<<640, 256>>>(m1w, m2w, pw, features);
    hgemm<<<dim3(16, 12), 256, GEMM_SMEM>>>(0, m1b, bboxes, nullptr);
    hgemm<<<dim3(16, 12), 256, GEMM_SMEM>>>(1, m2b, bboxes, nullptr);

    // join, then tail (needs both branches)
    cudaStreamWaitEvent(0, eJoin, 0);
    hb_kernel<<<24, 256>>>(pw, pb);
    hgemm<<<dim3(16, 12), 256, GEMM_SMEM>>>(2, nullptr, bboxes, out_vis);
}